// round 13
// baseline (speedup 1.0000x reference)
#include <cuda_runtime.h>
#include <cstdint>

#define DIMS   1000
#define NLEV   10
#define NPIX   784
#define NBATCH 256
#define NCLS   10
#define PW     25      // 784 pixels -> 25 x u32 words
#define PWP    28      // g_posb row stride in words (112B)

// ---------------- device scratch (no allocations allowed) ----------------
__device__ uint32_t g_posb[1024 * PWP];   // packed position sign bits, d-major rows

__device__ __forceinline__ uint32_t smem_u32(const void* p) {
    uint32_t a;
    asm("{ .reg .u64 t; cvta.to.shared.u64 t, %1; cvt.u32.u64 %0, t; }"
        : "=r"(a) : "l"(p));
    return a;
}

// ---------------- kernel A: pack position sign bits via cp.async.bulk ----
// CTA (w, qq): bulk-copies 8 rows (32KB) of position into smem, packs 8 bits
// per dim, stores them as byte qq of word w in g_posb (byte stores compose
// words across CTAs without RMW -> deterministic).
__global__ __launch_bounds__(256) void pack_kernel(const float* __restrict__ position) {
    __shared__ __align__(128) float buf[8 * DIMS];        // 32000 B
    __shared__ __align__(8) unsigned long long mbar;

    const int w   = blockIdx.x;            // 0..24
    const int qq  = blockIdx.y;            // 0..3
    const int tid = threadIdx.x;
    const int p0  = w * 32 + qq * 8;       // first pixel of this byte
    const bool active = (p0 < NPIX);       // 784 = 98*8: active => full 8 rows

    if (active) {
        uint32_t mb = smem_u32(&mbar);
        if (tid == 0) {
            asm volatile("mbarrier.init.shared.b64 [%0], %1;"
                         :: "r"(mb), "r"(1) : "memory");
        }
        __syncthreads();
        if (tid == 0) {
            const uint32_t bytes = 8 * DIMS * 4;   // 32000, 16B multiple
            asm volatile("mbarrier.arrive.expect_tx.shared.b64 _, [%0], %1;"
                         :: "r"(mb), "r"(bytes) : "memory");
            asm volatile(
                "cp.async.bulk.shared::cluster.global.mbarrier::complete_tx::bytes "
                "[%0], [%1], %2, [%3];"
                :: "r"(smem_u32(buf)),
                   "l"(position + (size_t)p0 * DIMS),
                   "r"(bytes), "r"(mb) : "memory");
        }
        uint32_t mb2 = smem_u32(&mbar);
        uint32_t done;
        asm volatile(
            "{\n\t.reg .pred p;\n\t"
            "mbarrier.try_wait.parity.acquire.cta.shared::cta.b64 p, [%1], 0;\n\t"
            "selp.b32 %0, 1, 0, p;\n\t}"
            : "=r"(done) : "r"(mb2) : "memory");
        while (!done) {
            asm volatile(
                "{\n\t.reg .pred p;\n\t"
                "mbarrier.try_wait.parity.acquire.cta.shared::cta.b64 p, [%1], 0, 0x989680;\n\t"
                "selp.b32 %0, 1, 0, p;\n\t}"
                : "=r"(done) : "r"(mb2) : "memory");
        }
    }

    if (tid < 250) {
        const int d0 = tid * 4;
        uint32_t b0 = 0, b1 = 0, b2 = 0, b3 = 0;
        if (active) {
#pragma unroll
            for (int j = 0; j < 8; j++) {
                float4 v = ((const float4*)buf)[j * 250 + tid];
                b0 |= (v.x > 0.0f ? 1u : 0u) << j;
                b1 |= (v.y > 0.0f ? 1u : 0u) << j;
                b2 |= (v.z > 0.0f ? 1u : 0u) << j;
                b3 |= (v.w > 0.0f ? 1u : 0u) << j;
            }
        }
        unsigned char* gb = (unsigned char*)g_posb;
        const int off = w * 4 + qq;            // byte offset inside the row
        gb[(size_t)(d0 + 0) * (PWP * 4) + off] = (unsigned char)b0;
        gb[(size_t)(d0 + 1) * (PWP * 4) + off] = (unsigned char)b1;
        gb[(size_t)(d0 + 2) * (PWP * 4) + off] = (unsigned char)b2;
        gb[(size_t)(d0 + 3) * (PWP * 4) + off] = (unsigned char)b3;
    }
}

// ---------------- kernel B: 256 CTAs x 256 thr, one batch each ----------
// Thread owns dims 4t..4t+3 (named-reg loads, no spill). Ballot masks ->
// wide phase-2 union build -> popcount -> nibble-packed enc -> warp GEMV.
__global__ __launch_bounds__(256, 2) void hdc_kernel(const float* __restrict__ x,
                                                     const float* __restrict__ vt,
                                                     const float* __restrict__ W,
                                                     float* __restrict__ out) {
    __shared__ uint32_t MunT[2][PW][32];   // [half][word][sg]  6.4KB
    __shared__ int      Cun[2][32];
    __shared__ uint32_t mask[NLEV][PW];
    __shared__ int      cnt[NLEV];
    __shared__ uint32_t encn[256];         // 4 enc bits per thread

    const int b    = blockIdx.x;
    const int tid  = threadIdx.x;
    const int lane = tid & 31;
    const int warp = tid >> 5;
    const bool hasd = (tid < 250);

    // ---- early: vt signatures for this thread's 4 dims (float4 loads) ----
    uint32_t sig[4] = {0u, 0u, 0u, 0u};
    if (hasd) {
#pragma unroll
        for (int l = 0; l < NLEV; l++) {
            float4 vv = *(const float4*)(vt + l * DIMS + 4 * tid);
            sig[0] |= (vv.x > 0.0f ? 1u : 0u) << l;
            sig[1] |= (vv.y > 0.0f ? 1u : 0u) << l;
            sig[2] |= (vv.z > 0.0f ? 1u : 0u) << l;
            sig[3] |= (vv.w > 0.0f ? 1u : 0u) << l;
        }
    }
    // early pixel loads (4 independent)
    const float* xb = x + b * NPIX;
    float xv[4];
#pragma unroll
    for (int r = 0; r < 4; r++) {
        int p = r * 256 + tid;
        xv[r] = (p < NPIX) ? xb[p] : -1.0f;
    }

    // ---- phase 1: level masks via ballot ----
#pragma unroll
    for (int r = 0; r < 4; r++) {
        int p = r * 256 + tid;
        int lvl = -1;
        if (p < NPIX) {
            int q = (int)rintf(xv[r] * 9.0f);     // round-half-even == jnp.round
            q = q < 0 ? 0 : (q > 9 ? 9 : q);
            lvl = q;
        }
        int word = r * 8 + warp;
#pragma unroll
        for (int l = 0; l < NLEV; l++) {
            unsigned bm = __ballot_sync(0xffffffffu, lvl == l);
            if (lane == 0 && word < PW) mask[l][word] = bm;
        }
    }
    __syncthreads();

    if (tid < NLEV) {
        int c = 0;
#pragma unroll
        for (int w = 0; w < PW; w++) c += __popc(mask[tid][w]);
        cnt[tid] = c;
    }
    __syncthreads();

    // ---- phase 2: unions, 256-wide: thread = (word-group, half, sg) ----
    {
        int qg   = tid >> 6;            // 0..3 word group
        int half = (tid >> 5) & 1;
        int sg   = tid & 31;
        int lbase = half * 5;
        uint32_t s0 = (sg & 1)  ? 0xffffffffu : 0u;
        uint32_t s1 = (sg & 2)  ? 0xffffffffu : 0u;
        uint32_t s2 = (sg & 4)  ? 0xffffffffu : 0u;
        uint32_t s3 = (sg & 8)  ? 0xffffffffu : 0u;
        uint32_t s4 = (sg & 16) ? 0xffffffffu : 0u;
        int q0 = qg * 7;
        int q1 = q0 + 7; if (q1 > PW) q1 = PW;
        for (int q = q0; q < q1; q++) {
            uint32_t m0 = mask[lbase + 0][q];
            uint32_t m1 = mask[lbase + 1][q];
            uint32_t m2 = mask[lbase + 2][q];
            uint32_t m3 = mask[lbase + 3][q];
            uint32_t m4 = mask[lbase + 4][q];
            MunT[half][q][sg] =
                (m0 & s0) | (m1 & s1) | (m2 & s2) | (m3 & s3) | (m4 & s4);
        }
        if (qg == 0) {
            int c = 0;
#pragma unroll
            for (int l = 0; l < 5; l++)
                if (sg & (1 << l)) c += cnt[lbase + l];
            Cun[half][sg] = c;
        }
    }
    __syncthreads();

    // ---- phase 3: 4 dims per thread, named-reg loads, nibble pack ----
    uint32_t nib = 0u;
    if (hasd) {
#pragma unroll
        for (int j = 0; j < 4; j++) {
            const int d = 4 * tid + j;
            const uint4* p4 = (const uint4*)&g_posb[d * PWP];
            uint4 A = p4[0], B = p4[1], C = p4[2], D = p4[3], E = p4[4], F = p4[5];
            uint32_t P = g_posb[d * PWP + 24];
            const int lo = sig[j] & 31, hi = (sig[j] >> 5) & 31;
            int tot = __popc(A.x) + __popc(A.y) + __popc(A.z) + __popc(A.w)
                    + __popc(B.x) + __popc(B.y) + __popc(B.z) + __popc(B.w)
                    + __popc(C.x) + __popc(C.y) + __popc(C.z) + __popc(C.w)
                    + __popc(D.x) + __popc(D.y) + __popc(D.z) + __popc(D.w)
                    + __popc(E.x) + __popc(E.y) + __popc(E.z) + __popc(E.w)
                    + __popc(F.x) + __popc(F.y) + __popc(F.z) + __popc(F.w)
                    + __popc(P);
            int acc = 0;
#define WORDOP(pw, qi) { uint32_t u = MunT[0][qi][lo] | MunT[1][qi][hi]; \
                         acc += __popc(u & (pw)); }
            WORDOP(A.x, 0)  WORDOP(A.y, 1)  WORDOP(A.z, 2)  WORDOP(A.w, 3)
            WORDOP(B.x, 4)  WORDOP(B.y, 5)  WORDOP(B.z, 6)  WORDOP(B.w, 7)
            WORDOP(C.x, 8)  WORDOP(C.y, 9)  WORDOP(C.z, 10) WORDOP(C.w, 11)
            WORDOP(D.x, 12) WORDOP(D.y, 13) WORDOP(D.z, 14) WORDOP(D.w, 15)
            WORDOP(E.x, 16) WORDOP(E.y, 17) WORDOP(E.z, 18) WORDOP(E.w, 19)
            WORDOP(F.x, 20) WORDOP(F.y, 21) WORDOP(F.z, 22) WORDOP(F.w, 23)
            WORDOP(P, 24)
#undef WORDOP
            int s = 4 * acc - 2 * (Cun[0][lo] + Cun[1][hi]) - (2 * tot - NPIX);
            nib |= (s > 0 ? 1u : 0u) << j;
        }
    }
    encn[tid] = nib;
    __syncthreads();

    // ---- stage 2: classifier GEMV (coalesced float4 W, fixed order) ----
#pragma unroll
    for (int cc = 0; cc < 2; cc++) {
        int c = warp + cc * 8;
        if (c < NCLS) {
            float acc = 0.0f;
#pragma unroll
            for (int k = 0; k < 8; k++) {
                int t = k * 32 + lane;
                if (t < 250) {
                    uint32_t nb = encn[t];
                    float4 wv = ((const float4*)(W + c * DIMS))[t];
                    acc += (nb & 1u) ? wv.x : -wv.x;
                    acc += (nb & 2u) ? wv.y : -wv.y;
                    acc += (nb & 4u) ? wv.z : -wv.z;
                    acc += (nb & 8u) ? wv.w : -wv.w;
                }
            }
            acc += __shfl_down_sync(0xffffffffu, acc, 16);
            acc += __shfl_down_sync(0xffffffffu, acc, 8);
            acc += __shfl_down_sync(0xffffffffu, acc, 4);
            acc += __shfl_down_sync(0xffffffffu, acc, 2);
            acc += __shfl_down_sync(0xffffffffu, acc, 1);
            if (lane == 0) out[b * NCLS + c] = acc;
        }
    }
}

// ---------------- launch ----------------
extern "C" void kernel_launch(void* const* d_in, const int* in_sizes, int n_in,
                              void* d_out, int out_size) {
    const float* x        = (const float*)d_in[0];   // [256, 28, 28]
    const float* position = (const float*)d_in[1];   // [784, 1000]
    const float* vt       = (const float*)d_in[2];   // [10, 1000]
    const float* W        = (const float*)d_in[3];   // [10, 1000]
    float* out = (float*)d_out;                      // [256, 10]

    pack_kernel<<<dim3(25, 4), 256>>>(position);
    hdc_kernel<<<256, 256>>>(x, vt, W, out);
}

// round 16
// speedup vs baseline: 1.0034x; 1.0034x over previous
#include <cuda_runtime.h>
#include <cstdint>

#define DIMS   1000
#define NLEV   10
#define NPIX   784
#define NBATCH 256
#define NCLS   10
#define PW     25      // 784 pixels -> 25 x u32 words
#define PWP    28      // g_posb row stride in words (112B)

// ---------------- device scratch (no allocations allowed) ----------------
__device__ uint32_t g_posb[1024 * PWP];   // packed position sign bits, d-major rows

__device__ __forceinline__ uint32_t smem_u32(const void* p) {
    uint32_t a;
    asm("{ .reg .u64 t; cvta.to.shared.u64 t, %1; cvt.u32.u64 %0, t; }"
        : "=r"(a) : "l"(p));
    return a;
}

// ---------------- kernel A: pack position sign bits via cp.async.bulk ----
// CTA (w, qq): bulk-copies 8 rows (32KB) of position into smem, packs 8 bits
// per dim, stores them as byte qq of word w in g_posb. CTA (0,0) also zeroes
// the output buffer (stream-ordered before hdc's atomics).
__global__ __launch_bounds__(256) void pack_kernel(const float* __restrict__ position,
                                                   float* __restrict__ out) {
    __shared__ __align__(128) float buf[8 * DIMS];        // 32000 B
    __shared__ __align__(8) unsigned long long mbar;

    const int w   = blockIdx.x;            // 0..24
    const int qq  = blockIdx.y;            // 0..3
    const int tid = threadIdx.x;
    const int p0  = w * 32 + qq * 8;       // first pixel of this byte
    const bool active = (p0 < NPIX);       // 784 = 98*8: active => full 8 rows

    if (active) {
        uint32_t mb = smem_u32(&mbar);
        if (tid == 0) {
            asm volatile("mbarrier.init.shared.b64 [%0], %1;"
                         :: "r"(mb), "r"(1) : "memory");
        }
        __syncthreads();
        if (tid == 0) {
            const uint32_t bytes = 8 * DIMS * 4;   // 32000, 16B multiple
            asm volatile("mbarrier.arrive.expect_tx.shared.b64 _, [%0], %1;"
                         :: "r"(mb), "r"(bytes) : "memory");
            asm volatile(
                "cp.async.bulk.shared::cluster.global.mbarrier::complete_tx::bytes "
                "[%0], [%1], %2, [%3];"
                :: "r"(smem_u32(buf)),
                   "l"(position + (size_t)p0 * DIMS),
                   "r"(bytes), "r"(mb) : "memory");
        }
        uint32_t mb2 = smem_u32(&mbar);
        uint32_t done;
        asm volatile(
            "{\n\t.reg .pred p;\n\t"
            "mbarrier.try_wait.parity.acquire.cta.shared::cta.b64 p, [%1], 0;\n\t"
            "selp.b32 %0, 1, 0, p;\n\t}"
            : "=r"(done) : "r"(mb2) : "memory");
        while (!done) {
            asm volatile(
                "{\n\t.reg .pred p;\n\t"
                "mbarrier.try_wait.parity.acquire.cta.shared::cta.b64 p, [%1], 0, 0x989680;\n\t"
                "selp.b32 %0, 1, 0, p;\n\t}"
                : "=r"(done) : "r"(mb2) : "memory");
        }
    }

    if (tid < 250) {
        const int d0 = tid * 4;
        uint32_t b0 = 0, b1 = 0, b2 = 0, b3 = 0;
        if (active) {
#pragma unroll
            for (int j = 0; j < 8; j++) {
                float4 v = ((const float4*)buf)[j * 250 + tid];
                b0 |= (v.x > 0.0f ? 1u : 0u) << j;
                b1 |= (v.y > 0.0f ? 1u : 0u) << j;
                b2 |= (v.z > 0.0f ? 1u : 0u) << j;
                b3 |= (v.w > 0.0f ? 1u : 0u) << j;
            }
        }
        unsigned char* gb = (unsigned char*)g_posb;
        const int off = w * 4 + qq;            // byte offset inside the row
        gb[(size_t)(d0 + 0) * (PWP * 4) + off] = (unsigned char)b0;
        gb[(size_t)(d0 + 1) * (PWP * 4) + off] = (unsigned char)b1;
        gb[(size_t)(d0 + 2) * (PWP * 4) + off] = (unsigned char)b2;
        gb[(size_t)(d0 + 3) * (PWP * 4) + off] = (unsigned char)b3;
    }
    // zero the output buffer once (runs before hdc in stream order)
    if (w == 0 && qq == 0) {
        for (int i = tid; i < NBATCH * NCLS; i += 256) out[i] = 0.0f;
    }
}

// ---------------- kernel B: 1024 CTAs = (batch, dim-group) ---------------
// Each CTA builds its batch's tables and handles 250 dims (1 dim/thread,
// named regs). Partial logits combined by atomicAdd (out pre-zeroed).
__global__ __launch_bounds__(256, 4) void hdc_kernel(const float* __restrict__ x,
                                                     const float* __restrict__ vt,
                                                     const float* __restrict__ W,
                                                     float* __restrict__ out) {
    __shared__ uint32_t MunT[2][PW][32];   // [half][word][sg]  6.4KB
    __shared__ int      Cun[2][32];
    __shared__ uint32_t mask[NLEV][PW];
    __shared__ int      cnt[NLEV];
    __shared__ uint32_t encw[8];           // ballot-packed enc bits

    const int b    = blockIdx.x;           // batch
    const int dg   = blockIdx.y;           // dim group 0..3
    const int tid  = threadIdx.x;
    const int lane = tid & 31;
    const int warp = tid >> 5;
    const bool hasd = (tid < 250);
    const int d    = dg * 250 + tid;       // this thread's dim

    // ---- hoisted global loads (hide behind ballot/union phases) ----
    uint4 pA = {0,0,0,0}, pB = {0,0,0,0}, pC = {0,0,0,0},
          pD = {0,0,0,0}, pE = {0,0,0,0}, pF = {0,0,0,0};
    uint32_t p24 = 0, sig = 0;
    if (hasd) {
        const uint4* p4 = (const uint4*)&g_posb[d * PWP];
        pA = p4[0]; pB = p4[1]; pC = p4[2]; pD = p4[3]; pE = p4[4]; pF = p4[5];
        p24 = g_posb[d * PWP + 24];
#pragma unroll
        for (int l = 0; l < NLEV; l++)
            sig |= (vt[l * DIMS + d] > 0.0f ? 1u : 0u) << l;
    }
    const float* xb = x + b * NPIX;
    float xv[4];
#pragma unroll
    for (int r = 0; r < 4; r++) {
        int p = r * 256 + tid;
        xv[r] = (p < NPIX) ? xb[p] : -1.0f;
    }

    // ---- phase 1: level masks via ballot ----
#pragma unroll
    for (int r = 0; r < 4; r++) {
        int p = r * 256 + tid;
        int lvl = -1;
        if (p < NPIX) {
            int q = (int)rintf(xv[r] * 9.0f);     // round-half-even == jnp.round
            q = q < 0 ? 0 : (q > 9 ? 9 : q);
            lvl = q;
        }
        int word = r * 8 + warp;
#pragma unroll
        for (int l = 0; l < NLEV; l++) {
            unsigned bm = __ballot_sync(0xffffffffu, lvl == l);
            if (lane == 0 && word < PW) mask[l][word] = bm;
        }
    }
    __syncthreads();

    if (tid < NLEV) {
        int c = 0;
#pragma unroll
        for (int w = 0; w < PW; w++) c += __popc(mask[tid][w]);
        cnt[tid] = c;
    }
    __syncthreads();

    // ---- phase 2: unions, 256-wide: thread = (word-group, half, sg) ----
    {
        int qg   = tid >> 6;            // 0..3 word group
        int half = (tid >> 5) & 1;
        int sg   = tid & 31;
        int lbase = half * 5;
        uint32_t s0 = (sg & 1)  ? 0xffffffffu : 0u;
        uint32_t s1 = (sg & 2)  ? 0xffffffffu : 0u;
        uint32_t s2 = (sg & 4)  ? 0xffffffffu : 0u;
        uint32_t s3 = (sg & 8)  ? 0xffffffffu : 0u;
        uint32_t s4 = (sg & 16) ? 0xffffffffu : 0u;
        int q0 = qg * 7;
        int q1 = q0 + 7; if (q1 > PW) q1 = PW;
        for (int q = q0; q < q1; q++) {
            uint32_t m0 = mask[lbase + 0][q];
            uint32_t m1 = mask[lbase + 1][q];
            uint32_t m2 = mask[lbase + 2][q];
            uint32_t m3 = mask[lbase + 3][q];
            uint32_t m4 = mask[lbase + 4][q];
            MunT[half][q][sg] =
                (m0 & s0) | (m1 & s1) | (m2 & s2) | (m3 & s3) | (m4 & s4);
        }
        if (qg == 0) {
            int c = 0;
#pragma unroll
            for (int l = 0; l < 5; l++)
                if (sg & (1 << l)) c += cnt[lbase + l];
            Cun[half][sg] = c;
        }
    }
    __syncthreads();

    // ---- phase 3: one dim per thread, enc via ballot ----
    bool bit = false;
    if (hasd) {
        const int lo = sig & 31, hi = (sig >> 5) & 31;
        int tot = __popc(pA.x) + __popc(pA.y) + __popc(pA.z) + __popc(pA.w)
                + __popc(pB.x) + __popc(pB.y) + __popc(pB.z) + __popc(pB.w)
                + __popc(pC.x) + __popc(pC.y) + __popc(pC.z) + __popc(pC.w)
                + __popc(pD.x) + __popc(pD.y) + __popc(pD.z) + __popc(pD.w)
                + __popc(pE.x) + __popc(pE.y) + __popc(pE.z) + __popc(pE.w)
                + __popc(pF.x) + __popc(pF.y) + __popc(pF.z) + __popc(pF.w)
                + __popc(p24);
        int acc = 0;
#define WORDOP(pw, qi) { uint32_t u = MunT[0][qi][lo] | MunT[1][qi][hi]; \
                         acc += __popc(u & (pw)); }
        WORDOP(pA.x, 0)  WORDOP(pA.y, 1)  WORDOP(pA.z, 2)  WORDOP(pA.w, 3)
        WORDOP(pB.x, 4)  WORDOP(pB.y, 5)  WORDOP(pB.z, 6)  WORDOP(pB.w, 7)
        WORDOP(pC.x, 8)  WORDOP(pC.y, 9)  WORDOP(pC.z, 10) WORDOP(pC.w, 11)
        WORDOP(pD.x, 12) WORDOP(pD.y, 13) WORDOP(pD.z, 14) WORDOP(pD.w, 15)
        WORDOP(pE.x, 16) WORDOP(pE.y, 17) WORDOP(pE.z, 18) WORDOP(pE.w, 19)
        WORDOP(pF.x, 20) WORDOP(pF.y, 21) WORDOP(pF.z, 22) WORDOP(pF.w, 23)
        WORDOP(p24, 24)
#undef WORDOP
        int s = 4 * acc - 2 * (Cun[0][lo] + Cun[1][hi]) - (2 * tot - NPIX);
        bit = (s > 0);
    }
    unsigned e = __ballot_sync(0xffffffffu, bit);
    if (lane == 0) encw[warp] = e;
    __syncthreads();

    // ---- stage 2: partial classifier GEMV over this dim group ----
#pragma unroll
    for (int cc = 0; cc < 2; cc++) {
        int c = warp + cc * 8;
        if (c < NCLS) {
            float acc = 0.0f;
#pragma unroll
            for (int k = 0; k < 8; k++) {
                int t = k * 32 + lane;
                if (t < 250) {
                    uint32_t eb = encw[k];                  // LDS broadcast
                    float wv = W[c * DIMS + dg * 250 + t];  // coalesced
                    acc += ((eb >> lane) & 1u) ? wv : -wv;
                }
            }
            acc += __shfl_down_sync(0xffffffffu, acc, 16);
            acc += __shfl_down_sync(0xffffffffu, acc, 8);
            acc += __shfl_down_sync(0xffffffffu, acc, 4);
            acc += __shfl_down_sync(0xffffffffu, acc, 2);
            acc += __shfl_down_sync(0xffffffffu, acc, 1);
            if (lane == 0) atomicAdd(&out[b * NCLS + c], acc);
        }
    }
}

// ---------------- launch ----------------
extern "C" void kernel_launch(void* const* d_in, const int* in_sizes, int n_in,
                              void* d_out, int out_size) {
    const float* x        = (const float*)d_in[0];   // [256, 28, 28]
    const float* position = (const float*)d_in[1];   // [784, 1000]
    const float* vt       = (const float*)d_in[2];   // [10, 1000]
    const float* W        = (const float*)d_in[3];   // [10, 1000]
    float* out = (float*)d_out;                      // [256, 10]

    pack_kernel<<<dim3(25, 4), 256>>>(position, out);
    hdc_kernel<<<dim3(256, 4), 256>>>(x, vt, W, out);
}